// round 4
// baseline (speedup 1.0000x reference)
#include <cuda_runtime.h>
#include <math.h>

// ---------------- packed f32x2 helpers (sm_100+) ----------------
__device__ __forceinline__ unsigned long long pk2(float lo, float hi) {
    unsigned long long r;
    asm("mov.b64 %0, {%1, %2};" : "=l"(r) : "f"(lo), "f"(hi));
    return r;
}
__device__ __forceinline__ void upk2(unsigned long long v, float& lo, float& hi) {
    asm("mov.b64 {%0, %1}, %2;" : "=f"(lo), "=f"(hi) : "l"(v));
}
__device__ __forceinline__ unsigned long long ffma2(unsigned long long a,
                                                    unsigned long long b,
                                                    unsigned long long c) {
    unsigned long long d;
    asm("fma.rn.f32x2 %0, %1, %2, %3;" : "=l"(d) : "l"(a), "l"(b), "l"(c));
    return d;
}

// ---------------- config ----------------
static constexpr int BM = 128;   // rows per CTA
static constexpr int BN = 64;    // experts (all)
static constexpr int BK = 32;    // k-tile
static constexpr int TH = 256;   // threads per CTA
static constexpr int AS_LD = 132;  // padded lda for As[k][m] (16B aligned rows, reduced bank conflicts)
static constexpr int BS_LD = 66;   // padded ldb for Bs[k][n] (u64 elems)
static constexpr int LS_LD = 65;   // padded row stride for logits staging

static constexpr int AS_BYTES = BK * AS_LD * 4;   // 16896
static constexpr int BS_BYTES = BK * BS_LD * 8;   // 16896

__global__ __launch_bounds__(TH, 1)
void topk_gate_kernel(const float* __restrict__ x,
                      const float* __restrict__ W,
                      const float* __restrict__ bias,
                      float* __restrict__ out,
                      int N, int D, int write_idx) {
    __shared__ __align__(16) unsigned char smem_raw[AS_BYTES + BS_BYTES];
    float (*As)[AS_LD] = reinterpret_cast<float (*)[AS_LD]>(smem_raw);
    unsigned long long (*Bs)[BS_LD] =
        reinterpret_cast<unsigned long long (*)[BS_LD]>(smem_raw + AS_BYTES);
    float* Ls = reinterpret_cast<float*>(smem_raw);  // 128 x 65 floats (reused after GEMM)

    const int tid = threadIdx.x;
    const int tx = tid & 15;   // N direction, TN=4
    const int ty = tid >> 4;   // M direction, TM=8 (4 packed pairs)
    const int row0 = blockIdx.x * BM;

    // bias for this thread's 4 expert columns (L1/L2 resident, tiny)
    float bj[4];
#pragma unroll
    for (int j = 0; j < 4; j++) bj[j] = bias[tx * 4 + j];

    // 16 packed accumulators: P[p][j] holds rows (ty*8+2p, ty*8+2p+1), col tx*4+j
    unsigned long long P[4][4];
#pragma unroll
    for (int p = 0; p < 4; p++)
#pragma unroll
        for (int j = 0; j < 4; j++) P[p][j] = 0ULL;

    const int ktiles = D / BK;
    for (int kt = 0; kt < ktiles; kt++) {
        // ---- fill A tile (transposed: As[k][m]) ----
        const float* xg = x + (size_t)row0 * D + (size_t)kt * BK;
#pragma unroll
        for (int li = 0; li < 4; li++) {
            int idx = tid + TH * li;         // 0..1023
            int m  = idx >> 3;               // 0..127
            int k4 = (idx & 7) * 4;          // 0,4,..,28
            float4 v = *reinterpret_cast<const float4*>(xg + (size_t)m * D + k4);
            As[k4 + 0][m] = v.x;
            As[k4 + 1][m] = v.y;
            As[k4 + 2][m] = v.z;
            As[k4 + 3][m] = v.w;
        }
        // ---- fill B tile (transposed + duplicated pairs: Bs[k][n] = {W[n][k], W[n][k]}) ----
        const float* wg = W + (size_t)kt * BK;
#pragma unroll
        for (int li = 0; li < 2; li++) {
            int idx = tid + TH * li;         // 0..511
            int n  = idx >> 3;               // 0..63
            int k4 = (idx & 7) * 4;
            float4 w = *reinterpret_cast<const float4*>(wg + (size_t)n * D + k4);
            Bs[k4 + 0][n] = pk2(w.x, w.x);
            Bs[k4 + 1][n] = pk2(w.y, w.y);
            Bs[k4 + 2][n] = pk2(w.z, w.z);
            Bs[k4 + 3][n] = pk2(w.w, w.w);
        }
        __syncthreads();

#pragma unroll
        for (int kk = 0; kk < BK; kk++) {
            ulonglong2 a01 = *reinterpret_cast<const ulonglong2*>(&As[kk][ty * 8]);
            ulonglong2 a23 = *reinterpret_cast<const ulonglong2*>(&As[kk][ty * 8 + 4]);
            ulonglong2 b01 = *reinterpret_cast<const ulonglong2*>(&Bs[kk][tx * 4]);
            ulonglong2 b23 = *reinterpret_cast<const ulonglong2*>(&Bs[kk][tx * 4 + 2]);

            P[0][0] = ffma2(a01.x, b01.x, P[0][0]);
            P[0][1] = ffma2(a01.x, b01.y, P[0][1]);
            P[0][2] = ffma2(a01.x, b23.x, P[0][2]);
            P[0][3] = ffma2(a01.x, b23.y, P[0][3]);

            P[1][0] = ffma2(a01.y, b01.x, P[1][0]);
            P[1][1] = ffma2(a01.y, b01.y, P[1][1]);
            P[1][2] = ffma2(a01.y, b23.x, P[1][2]);
            P[1][3] = ffma2(a01.y, b23.y, P[1][3]);

            P[2][0] = ffma2(a23.x, b01.x, P[2][0]);
            P[2][1] = ffma2(a23.x, b01.y, P[2][1]);
            P[2][2] = ffma2(a23.x, b23.x, P[2][2]);
            P[2][3] = ffma2(a23.x, b23.y, P[2][3]);

            P[3][0] = ffma2(a23.y, b01.x, P[3][0]);
            P[3][1] = ffma2(a23.y, b01.y, P[3][1]);
            P[3][2] = ffma2(a23.y, b23.x, P[3][2]);
            P[3][3] = ffma2(a23.y, b23.y, P[3][3]);
        }
        __syncthreads();
    }

    // ---- epilogue: logits (+bias) to smem ----
#pragma unroll
    for (int p = 0; p < 4; p++) {
#pragma unroll
        for (int j = 0; j < 4; j++) {
            float lo, hi;
            upk2(P[p][j], lo, hi);
            int n = tx * 4 + j;
            int m = ty * 8 + 2 * p;
            Ls[m * LS_LD + n]       = lo + bj[j];
            Ls[(m + 1) * LS_LD + n] = hi + bj[j];
        }
    }
    __syncthreads();

    // ---- cooperative zero of the gates block (d_out is poisoned) ----
    {
        float4 z4 = make_float4(0.f, 0.f, 0.f, 0.f);
        float4* og = reinterpret_cast<float4*>(out + (size_t)row0 * BN);
#pragma unroll
        for (int i = 0; i < (BM * BN / 4) / TH; i++)  // 8 iters
            og[i * TH + tid] = z4;
    }
    __syncthreads();

    // ---- per-row top-2 + softmax + scatter ----
    if (tid < BM) {
        const int r = tid;
        const float* lr = Ls + r * LS_LD;
        float v1 = -INFINITY, v2 = -INFINITY;
        int i1 = 0, i2 = 0;
#pragma unroll
        for (int j = 0; j < BN; j++) {
            float v = lr[j];
            if (v > v1) {
                v2 = v1; i2 = i1;
                v1 = v;  i1 = j;
            } else if (v > v2) {
                v2 = v; i2 = j;
            }
        }
        // softmax over the two selected logits (exact, numerically safe: v2 <= v1)
        float e = expf(v2 - v1);
        float denom = 1.0f + e;
        float p1 = 1.0f / denom;
        float p2 = e / denom;

        size_t gbase = ((size_t)row0 + r) * BN;
        out[gbase + i1] = p1;
        out[gbase + i2] = p2;

        if (write_idx) {
            float* oi = out + (size_t)N * BN + ((size_t)row0 + r) * 2;
            oi[0] = (float)i1;
            oi[1] = (float)i2;
        }
    }
}

extern "C" void kernel_launch(void* const* d_in, const int* in_sizes, int n_in,
                              void* d_out, int out_size) {
    const float* x    = (const float*)d_in[0];
    const float* W    = (const float*)d_in[1];
    const float* bias = (const float*)d_in[2];
    float* out = (float*)d_out;

    const int E = in_sizes[2];                 // 64
    const int D = in_sizes[1] / E;             // 4096
    const int N = in_sizes[0] / D;             // 16384

    const int write_idx = (out_size >= N * E + 2 * N) ? 1 : 0;

    dim3 grid(N / BM);
    topk_gate_kernel<<<grid, TH>>>(x, W, bias, out, N, D, write_idx);
}

// round 10
// speedup vs baseline: 1.5104x; 1.5104x over previous
#include <cuda_runtime.h>
#include <math.h>
#include <stdint.h>

// ================= config =================
static constexpr int BM = 128;
static constexpr int BN = 64;
static constexpr int TH = 256;

static constexpr int A_SPL   = 128 * 144;           // one bf16 split tile of A
static constexpr int B_SPL   = 64 * 144;            // one bf16 split tile of B
static constexpr int STG_SPL = 2 * A_SPL + 2 * B_SPL;   // 55296 (Ah, Am, Bh, Bm)
static constexpr int A_RAW   = 128 * 272;           // raw fp32 A tile (padded rows)
static constexpr int B_RAW   = 64 * 272;
static constexpr int STG_RAW = A_RAW + B_RAW;       // 52224
static constexpr int OFF_SPLIT = 1024;
static constexpr int OFF_RAW   = OFF_SPLIT + 2 * STG_SPL;   // 111616
static constexpr int SMEM_TOTAL = OFF_RAW + 2 * STG_RAW;    // 216064
static constexpr int LS_LD = 66;
#define THRESH 2e-4f

// ================= ptx helpers (all plain sm_80-level, no 'a' features) =====
__device__ __forceinline__ uint32_t s2u(const void* p) {
    uint32_t a;
    asm("{ .reg .u64 t; cvta.to.shared.u64 t, %1; cvt.u32.u64 %0, t; }"
        : "=r"(a) : "l"(p));
    return a;
}
// pack: lo half <- bf16(a), hi half <- bf16(b)
__device__ __forceinline__ uint32_t bf2pack(float a, float b) {
    uint32_t r;
    asm("cvt.rn.bf16x2.f32 %0, %1, %2;" : "=r"(r) : "f"(b), "f"(a));
    return r;
}
__device__ __forceinline__ float bflo(uint32_t h) { return __uint_as_float(h << 16); }
__device__ __forceinline__ float bfhi(uint32_t h) { return __uint_as_float(h & 0xFFFF0000u); }

__device__ __forceinline__ void cp16(uint32_t dst, const void* src) {
    asm volatile("cp.async.cg.shared.global [%0], [%1], 16;" :: "r"(dst), "l"(src) : "memory");
}
#define CP_COMMIT() asm volatile("cp.async.commit_group;" ::: "memory")
#define CP_WAIT1()  asm volatile("cp.async.wait_group 1;" ::: "memory")

__device__ __forceinline__ void ldsm4(uint32_t* r, uint32_t addr) {
    asm volatile("ldmatrix.sync.aligned.m8n8.x4.shared.b16 {%0,%1,%2,%3}, [%4];"
                 : "=r"(r[0]), "=r"(r[1]), "=r"(r[2]), "=r"(r[3]) : "r"(addr));
}
__device__ __forceinline__ void mma_bf16(float* c, const uint32_t* a, const uint32_t* b) {
    asm volatile(
        "mma.sync.aligned.m16n8k16.row.col.f32.bf16.bf16.f32 "
        "{%0,%1,%2,%3}, {%4,%5,%6,%7}, {%8,%9}, {%0,%1,%2,%3};"
        : "+f"(c[0]), "+f"(c[1]), "+f"(c[2]), "+f"(c[3])
        : "r"(a[0]), "r"(a[1]), "r"(a[2]), "r"(a[3]), "r"(b[0]), "r"(b[1]));
}

// ================= kernel =================
__global__ __launch_bounds__(TH, 1)
void topk_gate_hmma_kernel(const float* __restrict__ x,
                           const float* __restrict__ W,
                           const float* __restrict__ bias,
                           float* __restrict__ out,
                           int N, int D, int write_idx) {
    extern __shared__ __align__(16) char smem[];
    const uint32_t sb = s2u(smem);
    const int tid = threadIdx.x;
    const int lane = tid & 31;
    const int wid = tid >> 5;
    const int row0 = blockIdx.x * BM;

    if (tid < BN) ((float*)smem)[tid] = bias[tid];

    // ---- cp.async geometry ----
    const int rowA = tid & 127, ksA = tid >> 7;          // A: 32 elems each
    const int rowB = tid & 63,  ksB = tid >> 6;          // B: 16 elems each
    const float* gA = x + (size_t)(row0 + rowA) * D + ksA * 32;
    const float* gB = W + (size_t)rowB * D + ksB * 16;
    const uint32_t dA_raw = sb + OFF_RAW + rowA * 272 + ksA * 128;
    const uint32_t dB_raw = sb + OFF_RAW + A_RAW + rowB * 272 + ksB * 64;

    const int ktiles = D / 64;

    // prolog: tiles 0, 1
#pragma unroll
    for (int t = 0; t < 2; t++) {
        uint32_t so = t * STG_RAW;
#pragma unroll
        for (int i = 0; i < 8; i++) cp16(dA_raw + so + i * 16, gA + (size_t)t * 64 + i * 4);
#pragma unroll
        for (int i = 0; i < 4; i++) cp16(dB_raw + so + i * 16, gB + (size_t)t * 64 + i * 4);
        CP_COMMIT();
    }

    // ---- MMA lane geometry (warp = wm in M x wn in N) ----
    const int wm = wid >> 1, wn = wid & 1;
    const int ar = wm * 32 + (lane & 15);
    uint32_t aoff[2], aqx[2];
#pragma unroll
    for (int mi = 0; mi < 2; mi++) {
        int r = ar + mi * 16;
        aoff[mi] = (uint32_t)r * 144;
        aqx[mi] = (uint32_t)((r >> 3) & 3) << 4;
    }
    const uint32_t ah16 = (uint32_t)(lane >> 4) * 16;
    const int br = wn * 32 + ((lane >> 4) << 3) + (lane & 7);
    uint32_t boff[2], bqx[2];
#pragma unroll
    for (int g = 0; g < 2; g++) {
        int r = br + g * 16;
        boff[g] = (uint32_t)r * 144;
        bqx[g] = (uint32_t)((r >> 3) & 3) << 4;
    }
    const uint32_t bh16 = (uint32_t)((lane >> 3) & 1) << 4;

    float acc[2][4][4];
#pragma unroll
    for (int mi = 0; mi < 2; mi++)
#pragma unroll
        for (int ni = 0; ni < 4; ni++)
#pragma unroll
            for (int q = 0; q < 4; q++) acc[mi][ni][q] = 0.0f;

    const uint32_t qxA = (uint32_t)((rowA >> 3) & 3) << 4;
    const uint32_t qxB = (uint32_t)((rowB >> 3) & 3) << 4;

    for (int kt = 0; kt < ktiles; kt++) {
        const int s = kt & 1;
        CP_WAIT1();
        __syncthreads();

        // ---- convert raw fp32 -> bf16 split tiles ----
        {
            const float4* ra = (const float4*)(smem + OFF_RAW + s * STG_RAW + rowA * 272 + ksA * 128);
            char* wa_h = smem + OFF_SPLIT + s * STG_SPL + rowA * 144;
            char* wa_m = wa_h + A_SPL;
            const uint32_t kb = (uint32_t)ksA * 64;  // byte base within split row
#pragma unroll
            for (int g = 0; g < 4; g++) {
                float4 u = ra[2 * g], v = ra[2 * g + 1];
                uint4 H, M;
                H.x = bf2pack(u.x, u.y); H.y = bf2pack(u.z, u.w);
                H.z = bf2pack(v.x, v.y); H.w = bf2pack(v.z, v.w);
                M.x = bf2pack(u.x - bflo(H.x), u.y - bfhi(H.x));
                M.y = bf2pack(u.z - bflo(H.y), u.w - bfhi(H.y));
                M.z = bf2pack(v.x - bflo(H.z), v.y - bfhi(H.z));
                M.w = bf2pack(v.z - bflo(H.w), v.w - bfhi(H.w));
                uint32_t off = (kb + g * 16) ^ qxA;
                *(uint4*)(wa_h + off) = H;
                *(uint4*)(wa_m + off) = M;
            }
            const float4* rb = (const float4*)(smem + OFF_RAW + s * STG_RAW + A_RAW + rowB * 272 + ksB * 64);
            char* wb_h = smem + OFF_SPLIT + s * STG_SPL + 2 * A_SPL + rowB * 144;
            char* wb_m = wb_h + B_SPL;
            const uint32_t kbb = (uint32_t)ksB * 32;
#pragma unroll
            for (int g = 0; g < 2; g++) {
                float4 u = rb[2 * g], v = rb[2 * g + 1];
                uint4 H, M;
                H.x = bf2pack(u.x, u.y); H.y = bf2pack(u.z, u.w);
                H.z = bf2pack(v.x, v.y); H.w = bf2pack(v.z, v.w);
                M.x = bf2pack(u.x - bflo(H.x), u.y - bfhi(H.x));
                M.y = bf2pack(u.z - bflo(H.y), u.w - bfhi(H.y));
                M.z = bf2pack(v.x - bflo(H.z), v.y - bfhi(H.z));
                M.w = bf2pack(v.z - bflo(H.w), v.w - bfhi(H.w));
                uint32_t off = (kbb + g * 16) ^ qxB;
                *(uint4*)(wb_h + off) = H;
                *(uint4*)(wb_m + off) = M;
            }
        }
        __syncthreads();

        // ---- prefetch tile kt+2 into the raw buffer just freed ----
        if (kt + 2 < ktiles) {
            uint32_t so = s * STG_RAW;
            const float* a = gA + (size_t)(kt + 2) * 64;
            const float* b = gB + (size_t)(kt + 2) * 64;
#pragma unroll
            for (int i = 0; i < 8; i++) cp16(dA_raw + so + i * 16, a + i * 4);
#pragma unroll
            for (int i = 0; i < 4; i++) cp16(dB_raw + so + i * 16, b + i * 4);
        }
        CP_COMMIT();

        // ---- MMA on split tiles of stage s ----
        const uint32_t Ah = sb + OFF_SPLIT + s * STG_SPL;
        const uint32_t Am = Ah + A_SPL;
        const uint32_t Bh = Ah + 2 * A_SPL;
        const uint32_t Bm = Bh + B_SPL;
#pragma unroll
        for (int ks = 0; ks < 4; ks++) {
            uint32_t ah[2][4], am[2][4], bh[4][2], bm[4][2];
            const uint32_t ka = (uint32_t)ks * 32 + ah16;
            const uint32_t kb2 = (uint32_t)ks * 32 + bh16;
            ldsm4(ah[0], Ah + aoff[0] + (ka ^ aqx[0]));
            ldsm4(ah[1], Ah + aoff[1] + (ka ^ aqx[1]));
            ldsm4(am[0], Am + aoff[0] + (ka ^ aqx[0]));
            ldsm4(am[1], Am + aoff[1] + (ka ^ aqx[1]));
            uint32_t t4[4];
            ldsm4(t4, Bh + boff[0] + (kb2 ^ bqx[0]));
            bh[0][0] = t4[0]; bh[0][1] = t4[1]; bh[1][0] = t4[2]; bh[1][1] = t4[3];
            ldsm4(t4, Bh + boff[1] + (kb2 ^ bqx[1]));
            bh[2][0] = t4[0]; bh[2][1] = t4[1]; bh[3][0] = t4[2]; bh[3][1] = t4[3];
            ldsm4(t4, Bm + boff[0] + (kb2 ^ bqx[0]));
            bm[0][0] = t4[0]; bm[0][1] = t4[1]; bm[1][0] = t4[2]; bm[1][1] = t4[3];
            ldsm4(t4, Bm + boff[1] + (kb2 ^ bqx[1]));
            bm[2][0] = t4[0]; bm[2][1] = t4[1]; bm[3][0] = t4[2]; bm[3][1] = t4[3];

#pragma unroll
            for (int mi = 0; mi < 2; mi++)
#pragma unroll
                for (int ni = 0; ni < 4; ni++) {
                    mma_bf16(acc[mi][ni], ah[mi], bh[ni]);  // h*h
                    mma_bf16(acc[mi][ni], ah[mi], bm[ni]);  // h*m
                    mma_bf16(acc[mi][ni], am[mi], bh[ni]);  // m*h
                }
        }
        __syncthreads();
    }

    // ---- epilogue: logits (+bias) -> Ls (reuses raw region) ----
    float* Ls = (float*)(smem + OFF_RAW);
    const float* bias_sm = (const float*)smem;
#pragma unroll
    for (int mi = 0; mi < 2; mi++)
#pragma unroll
        for (int ni = 0; ni < 4; ni++) {
            int r0 = wm * 32 + mi * 16 + (lane >> 2);
            int c  = wn * 32 + ni * 8 + (lane & 3) * 2;
            float b0 = bias_sm[c], b1 = bias_sm[c + 1];
            *(float2*)(Ls + r0 * LS_LD + c) =
                make_float2(acc[mi][ni][0] + b0, acc[mi][ni][1] + b1);
            *(float2*)(Ls + (r0 + 8) * LS_LD + c) =
                make_float2(acc[mi][ni][2] + b0, acc[mi][ni][3] + b1);
        }
    __syncthreads();

    // ---- per-row top-3 scan, exact rescue for narrow gaps, softmax, scatter ----
    if (tid < BM) {
        const float* lr = Ls + tid * LS_LD;
        float v1 = -INFINITY, v2 = -INFINITY, v3 = -INFINITY;
        int i1 = 0, i2 = 0;
#pragma unroll
        for (int j = 0; j < BN; j++) {
            float v = lr[j];
            if (v > v1)      { v3 = v2; v2 = v1; i2 = i1; v1 = v; i1 = j; }
            else if (v > v2) { v3 = v2; v2 = v; i2 = j; }
            else if (v > v3) { v3 = v; }
        }
        bool flag = (v1 - v2 < THRESH) || (v2 - v3 < THRESH);

        // warp-cooperative exact fp32 recompute for flagged rows (rare)
        unsigned m = __ballot_sync(0xFFFFFFFFu, flag);
        while (m) {
            int rr = __ffs(m) - 1;
            m &= m - 1;
            int row = (wid << 5) + rr;
            const float4* xr = (const float4*)(x + (size_t)(row0 + row) * D);
            const float4* w0 = (const float4*)(W + (size_t)lane * D);
            const float4* w1 = (const float4*)(W + (size_t)(lane + 32) * D);
            float a0 = 0.f, a1 = 0.f;
            const int KQ = D / 4;
#pragma unroll 4
            for (int kq = 0; kq < KQ; kq++) {
                float4 xv = xr[kq], u = w0[kq], v = w1[kq];
                a0 = fmaf(xv.x, u.x, a0); a0 = fmaf(xv.y, u.y, a0);
                a0 = fmaf(xv.z, u.z, a0); a0 = fmaf(xv.w, u.w, a0);
                a1 = fmaf(xv.x, v.x, a1); a1 = fmaf(xv.y, v.y, a1);
                a1 = fmaf(xv.z, v.z, a1); a1 = fmaf(xv.w, v.w, a1);
            }
            float* wr = Ls + row * LS_LD;
            wr[lane]      = a0 + bias_sm[lane];
            wr[lane + 32] = a1 + bias_sm[lane + 32];
            __syncwarp();
        }
        if (flag) {
            v1 = -INFINITY; v2 = -INFINITY; i1 = 0; i2 = 0;
#pragma unroll
            for (int j = 0; j < BN; j++) {
                float v = lr[j];
                if (v > v1)      { v2 = v1; i2 = i1; v1 = v; i1 = j; }
                else if (v > v2) { v2 = v; i2 = j; }
            }
        }

        float e  = expf(v2 - v1);
        float p1 = 1.0f / (1.0f + e);
        float p2 = e * p1;

        float* orow = out + (size_t)(row0 + tid) * BN;
        float4 z = make_float4(0.f, 0.f, 0.f, 0.f);
#pragma unroll
        for (int q = 0; q < 16; q++) ((float4*)orow)[q] = z;
        orow[i1] = p1;
        orow[i2] = p2;

        if (write_idx) {
            float* oi = out + (size_t)N * BN + (size_t)(row0 + tid) * 2;
            oi[0] = (float)i1;
            oi[1] = (float)i2;
        }
    }
}

// ================= launch =================
extern "C" void kernel_launch(void* const* d_in, const int* in_sizes, int n_in,
                              void* d_out, int out_size) {
    const float* x    = (const float*)d_in[0];
    const float* W    = (const float*)d_in[1];
    const float* bias = (const float*)d_in[2];
    float* out = (float*)d_out;

    const int E = in_sizes[2];          // 64
    const int D = in_sizes[1] / E;      // 4096
    const int N = in_sizes[0] / D;      // 16384
    const int write_idx = (out_size >= N * E + 2 * N) ? 1 : 0;

    cudaFuncSetAttribute(topk_gate_hmma_kernel,
                         cudaFuncAttributeMaxDynamicSharedMemorySize, SMEM_TOTAL);
    topk_gate_hmma_kernel<<<N / BM, TH, SMEM_TOTAL>>>(x, W, bias, out, N, D, write_idx);
}

// round 11
// speedup vs baseline: 1.7724x; 1.1735x over previous
#include <cuda_runtime.h>
#include <math.h>
#include <stdint.h>

// ================= config =================
static constexpr int BM = 64;
static constexpr int BN = 64;
static constexpr int TH = 128;

static constexpr int A_SPL = 64 * 144;          // 9216 (one split of A tile)
static constexpr int B_SPL = 64 * 144;          // 9216
static constexpr int STG   = 2 * A_SPL + 2 * B_SPL;   // Ah, Am, Bh, Bm = 36864
static constexpr int OFF_SPLIT = 1024;          // header: bias
static constexpr int SMEM_TOTAL = OFF_SPLIT + 2 * STG;  // 74752 -> 2 CTAs/SM
static constexpr int LS_LD = 66;
#define THRESH 2e-4f

// precomputed bf16 splits of W (written by wsplit_kernel, read via cp.async)
__device__ unsigned short Wh_g[64 * 4096];
__device__ unsigned short Wm_g[64 * 4096];

// ================= ptx helpers (sm_80-level only) =================
__device__ __forceinline__ uint32_t s2u(const void* p) {
    uint32_t a;
    asm("{ .reg .u64 t; cvta.to.shared.u64 t, %1; cvt.u32.u64 %0, t; }"
        : "=r"(a) : "l"(p));
    return a;
}
__device__ __forceinline__ uint32_t bf2pack(float a, float b) {
    uint32_t r;
    asm("cvt.rn.bf16x2.f32 %0, %1, %2;" : "=r"(r) : "f"(b), "f"(a));
    return r;
}
__device__ __forceinline__ float bflo(uint32_t h) { return __uint_as_float(h << 16); }
__device__ __forceinline__ float bfhi(uint32_t h) { return __uint_as_float(h & 0xFFFF0000u); }

__device__ __forceinline__ void cp16(uint32_t dst, const void* src) {
    asm volatile("cp.async.cg.shared.global [%0], [%1], 16;" :: "r"(dst), "l"(src) : "memory");
}
#define CP_COMMIT() asm volatile("cp.async.commit_group;" ::: "memory")
#define CP_WAIT0()  asm volatile("cp.async.wait_group 0;" ::: "memory")

__device__ __forceinline__ void ldsm4(uint32_t* r, uint32_t addr) {
    asm volatile("ldmatrix.sync.aligned.m8n8.x4.shared.b16 {%0,%1,%2,%3}, [%4];"
                 : "=r"(r[0]), "=r"(r[1]), "=r"(r[2]), "=r"(r[3]) : "r"(addr));
}
__device__ __forceinline__ void mma_bf16(float* c, const uint32_t* a, const uint32_t* b) {
    asm volatile(
        "mma.sync.aligned.m16n8k16.row.col.f32.bf16.bf16.f32 "
        "{%0,%1,%2,%3}, {%4,%5,%6,%7}, {%8,%9}, {%0,%1,%2,%3};"
        : "+f"(c[0]), "+f"(c[1]), "+f"(c[2]), "+f"(c[3])
        : "r"(a[0]), "r"(a[1]), "r"(a[2]), "r"(a[3]), "r"(b[0]), "r"(b[1]));
}

// ================= W split precompute =================
__global__ void wsplit_kernel(const float* __restrict__ W) {
    int i = (blockIdx.x * blockDim.x + threadIdx.x) * 4;
    float4 v = *(const float4*)(W + i);
    uint32_t h0 = bf2pack(v.x, v.y), h1 = bf2pack(v.z, v.w);
    uint32_t m0 = bf2pack(v.x - bflo(h0), v.y - bfhi(h0));
    uint32_t m1 = bf2pack(v.z - bflo(h1), v.w - bfhi(h1));
    *(uint2*)(Wh_g + i) = make_uint2(h0, h1);
    *(uint2*)(Wm_g + i) = make_uint2(m0, m1);
}

// ================= main kernel =================
__global__ __launch_bounds__(TH, 2)
void topk_gate_hmma_kernel(const float* __restrict__ x,
                           const float* __restrict__ W,
                           const float* __restrict__ bias,
                           float* __restrict__ out,
                           int N, int D, int write_idx) {
    extern __shared__ __align__(16) char smem[];
    const uint32_t sb = s2u(smem);
    const int tid = threadIdx.x;
    const int lane = tid & 31;
    const int wid = tid >> 5;
    const int row0 = blockIdx.x * BM;

    if (tid < BN) ((float*)smem)[tid] = bias[tid];

    // ---- A load/convert geometry: thread owns half a row (32 floats) ----
    const int rowA = tid & 63, ksA = tid >> 6;
    const float* gA = x + (size_t)(row0 + rowA) * D + ksA * 32;
    const uint32_t qxA = ((uint32_t)(rowA >> 3) & 3) << 4;

    // ---- ldsm geometry: warp wid covers rows wid*16..+15, all 64 cols ----
    const int ar = wid * 16 + (lane & 15);
    const uint32_t aoff = (uint32_t)ar * 144;
    const uint32_t aqx  = ((uint32_t)(ar >> 3) & 3) << 4;
    const uint32_t ah16 = (uint32_t)(lane >> 4) << 4;
    uint32_t boff[4], bqx[4];
#pragma unroll
    for (int g = 0; g < 4; g++) {
        int br = ((lane >> 4) << 3) + (lane & 7) + g * 16;
        boff[g] = (uint32_t)br * 144;
        bqx[g]  = ((uint32_t)(br >> 3) & 3) << 4;
    }
    const uint32_t bh16 = ((uint32_t)(lane >> 3) & 1) << 4;

    float acc[8][4];
#pragma unroll
    for (int ni = 0; ni < 8; ni++)
#pragma unroll
        for (int q = 0; q < 4; q++) acc[ni][q] = 0.0f;

    const int ktiles = D / 64;

    // ---- helpers (inlined) ----
    auto issueB = [&](int kt, int s) {
        const uint32_t bsm = sb + OFF_SPLIT + s * STG + 2 * A_SPL;
#pragma unroll
        for (int j = 0; j < 8; j++) {
            int cid = tid + TH * j;            // 0..1023
            int spl = cid >> 9;                // 0: Bh, 1: Bm
            int rem = cid & 511;
            int n = rem >> 3, c = rem & 7;
            uint32_t qx = ((uint32_t)(n >> 3) & 3) << 4;
            uint32_t dst = bsm + spl * B_SPL + n * 144 + (((uint32_t)c * 16) ^ qx);
            const unsigned short* src =
                (spl ? Wm_g : Wh_g) + (size_t)n * D + (size_t)kt * 64 + c * 8;
            cp16(dst, src);
        }
    };
    auto convA = [&](const float4* av, int s) {
        char* ah_ = smem + OFF_SPLIT + s * STG + rowA * 144;
        char* am_ = ah_ + A_SPL;
#pragma unroll
        for (int g = 0; g < 4; g++) {
            float4 u = av[2 * g], v = av[2 * g + 1];
            uint4 H, M;
            H.x = bf2pack(u.x, u.y); H.y = bf2pack(u.z, u.w);
            H.z = bf2pack(v.x, v.y); H.w = bf2pack(v.z, v.w);
            M.x = bf2pack(u.x - bflo(H.x), u.y - bfhi(H.x));
            M.y = bf2pack(u.z - bflo(H.y), u.w - bfhi(H.y));
            M.z = bf2pack(v.x - bflo(H.z), v.y - bfhi(H.z));
            M.w = bf2pack(v.z - bflo(H.w), v.w - bfhi(H.w));
            uint32_t off = ((uint32_t)(ksA * 64 + g * 16)) ^ qxA;
            *(uint4*)(ah_ + off) = H;
            *(uint4*)(am_ + off) = M;
        }
    };

    // ---- prolog: stage 0 ----
    float4 av[8];
    issueB(0, 0);
    CP_COMMIT();
#pragma unroll
    for (int i = 0; i < 8; i++) av[i] = *(const float4*)(gA + i * 4);
    convA(av, 0);
    CP_WAIT0();
    __syncthreads();

    // ---- main loop: 1 sync/iter; convert(next) and MMA(current) overlap ----
    for (int kt = 0; kt < ktiles; kt++) {
        const int s = kt & 1, s2 = s ^ 1;
        const bool more = (kt + 1 < ktiles);
        if (more) {
            issueB(kt + 1, s2);
            const float* ga = gA + (size_t)(kt + 1) * 64;
#pragma unroll
            for (int i = 0; i < 8; i++) av[i] = *(const float4*)(ga + i * 4);
        }
        CP_COMMIT();

        const uint32_t Ah = sb + OFF_SPLIT + s * STG;
        const uint32_t Am = Ah + A_SPL;
        const uint32_t Bh = Ah + 2 * A_SPL;
        const uint32_t Bm = Bh + B_SPL;
#pragma unroll
        for (int ks = 0; ks < 4; ks++) {
            uint32_t ah[4], am[4], bh[8][2], bm[8][2], t4[4];
            const uint32_t ka = ((uint32_t)(ks * 32) + ah16) ^ aqx;
            ldsm4(ah, Ah + aoff + ka);
            ldsm4(am, Am + aoff + ka);
#pragma unroll
            for (int g = 0; g < 4; g++) {
                const uint32_t kb = ((uint32_t)(ks * 32) + bh16) ^ bqx[g];
                ldsm4(t4, Bh + boff[g] + kb);
                bh[2 * g][0] = t4[0]; bh[2 * g][1] = t4[1];
                bh[2 * g + 1][0] = t4[2]; bh[2 * g + 1][1] = t4[3];
                ldsm4(t4, Bm + boff[g] + kb);
                bm[2 * g][0] = t4[0]; bm[2 * g][1] = t4[1];
                bm[2 * g + 1][0] = t4[2]; bm[2 * g + 1][1] = t4[3];
            }
#pragma unroll
            for (int ni = 0; ni < 8; ni++) {
                mma_bf16(acc[ni], ah, bh[ni]);   // h*h
                mma_bf16(acc[ni], ah, bm[ni]);   // h*m
                mma_bf16(acc[ni], am, bh[ni]);   // m*h
            }
        }
        if (more) convA(av, s2);
        CP_WAIT0();
        __syncthreads();
    }

    // ---- epilogue: logits (+bias) -> Ls (reuses split area) ----
    float* Ls = (float*)(smem + OFF_SPLIT);
    const float* bias_sm = (const float*)smem;
    {
        const int r0 = wid * 16 + (lane >> 2);
        const int cbase = (lane & 3) * 2;
#pragma unroll
        for (int ni = 0; ni < 8; ni++) {
            int c = ni * 8 + cbase;
            float b0 = bias_sm[c], b1 = bias_sm[c + 1];
            *(float2*)(Ls + r0 * LS_LD + c) =
                make_float2(acc[ni][0] + b0, acc[ni][1] + b1);
            *(float2*)(Ls + (r0 + 8) * LS_LD + c) =
                make_float2(acc[ni][2] + b0, acc[ni][3] + b1);
        }
    }
    __syncthreads();

    // ---- per-row top-3 scan, exact fp32 rescue for narrow gaps, softmax ----
    if (tid < BM) {
        const float* lr = Ls + tid * LS_LD;
        float v1 = -INFINITY, v2 = -INFINITY, v3 = -INFINITY;
        int i1 = 0, i2 = 0;
#pragma unroll
        for (int j = 0; j < BN; j++) {
            float v = lr[j];
            if (v > v1)      { v3 = v2; v2 = v1; i2 = i1; v1 = v; i1 = j; }
            else if (v > v2) { v3 = v2; v2 = v; i2 = j; }
            else if (v > v3) { v3 = v; }
        }
        bool flag = (v1 - v2 < THRESH) || (v2 - v3 < THRESH);

        unsigned m = __ballot_sync(0xFFFFFFFFu, flag);
        while (m) {
            int rr = __ffs(m) - 1;
            m &= m - 1;
            int row = (wid << 5) + rr;
            const float4* xr = (const float4*)(x + (size_t)(row0 + row) * D);
            const float4* w0 = (const float4*)(W + (size_t)lane * D);
            const float4* w1 = (const float4*)(W + (size_t)(lane + 32) * D);
            float a0 = 0.f, a1 = 0.f;
            const int KQ = D / 4;
#pragma unroll 4
            for (int kq = 0; kq < KQ; kq++) {
                float4 xv = xr[kq], u = w0[kq], v = w1[kq];
                a0 = fmaf(xv.x, u.x, a0); a0 = fmaf(xv.y, u.y, a0);
                a0 = fmaf(xv.z, u.z, a0); a0 = fmaf(xv.w, u.w, a0);
                a1 = fmaf(xv.x, v.x, a1); a1 = fmaf(xv.y, v.y, a1);
                a1 = fmaf(xv.z, v.z, a1); a1 = fmaf(xv.w, v.w, a1);
            }
            float* wr = Ls + row * LS_LD;
            wr[lane]      = a0 + bias_sm[lane];
            wr[lane + 32] = a1 + bias_sm[lane + 32];
            __syncwarp();
        }
        if (flag) {
            v1 = -INFINITY; v2 = -INFINITY; i1 = 0; i2 = 0;
#pragma unroll
            for (int j = 0; j < BN; j++) {
                float v = lr[j];
                if (v > v1)      { v2 = v1; i2 = i1; v1 = v; i1 = j; }
                else if (v > v2) { v2 = v; i2 = j; }
            }
        }

        float e  = expf(v2 - v1);
        float p1 = 1.0f / (1.0f + e);
        float p2 = e * p1;

        float* orow = out + (size_t)(row0 + tid) * BN;
        float4 z = make_float4(0.f, 0.f, 0.f, 0.f);
#pragma unroll
        for (int q = 0; q < 16; q++) ((float4*)orow)[q] = z;
        orow[i1] = p1;
        orow[i2] = p2;

        if (write_idx) {
            float* oi = out + (size_t)N * BN + (size_t)(row0 + tid) * 2;
            oi[0] = (float)i1;
            oi[1] = (float)i2;
        }
    }
}

// ================= launch =================
extern "C" void kernel_launch(void* const* d_in, const int* in_sizes, int n_in,
                              void* d_out, int out_size) {
    const float* x    = (const float*)d_in[0];
    const float* W    = (const float*)d_in[1];
    const float* bias = (const float*)d_in[2];
    float* out = (float*)d_out;

    const int E = in_sizes[2];          // 64
    const int D = in_sizes[1] / E;      // 4096
    const int N = in_sizes[0] / D;      // 16384
    const int write_idx = (out_size >= N * E + 2 * N) ? 1 : 0;

    // 1) precompute bf16 splits of W (E*D elems, 4 per thread)
    wsplit_kernel<<<(E * D) / (256 * 4), 256>>>(W);

    // 2) fused gating kernel
    cudaFuncSetAttribute(topk_gate_hmma_kernel,
                         cudaFuncAttributeMaxDynamicSharedMemorySize, SMEM_TOTAL);
    topk_gate_hmma_kernel<<<N / BM, TH, SMEM_TOTAL>>>(x, W, bias, out, N, D, write_idx);
}

// round 14
// speedup vs baseline: 1.8443x; 1.0406x over previous
#include <cuda_runtime.h>
#include <math.h>
#include <stdint.h>

// ================= config =================
static constexpr int BM = 64;
static constexpr int BN = 64;
static constexpr int TH = 128;

static constexpr int B_SPL = 64 * 144;      // one bf16 split tile of B: 9216
static constexpr int STG   = 2 * B_SPL;     // Bh + Bm = 18432
static constexpr int OFF_SPLIT = 1024;      // header: bias
static constexpr int SMEM_BYTES = OFF_SPLIT + 2 * STG;   // 37888 (static)
static constexpr int LS_LD = 66;
#define THRESH 2e-4f

// precomputed bf16 splits of W (written by wsplit_kernel, read via cp.async)
__device__ unsigned short Wh_g[64 * 4096];
__device__ unsigned short Wm_g[64 * 4096];

// ================= ptx helpers (sm_80-level only) =================
__device__ __forceinline__ uint32_t s2u(const void* p) {
    uint32_t a;
    asm("{ .reg .u64 t; cvta.to.shared.u64 t, %1; cvt.u32.u64 %0, t; }"
        : "=r"(a) : "l"(p));
    return a;
}
__device__ __forceinline__ uint32_t bf2pack(float a, float b) {
    uint32_t r;
    asm("cvt.rn.bf16x2.f32 %0, %1, %2;" : "=r"(r) : "f"(b), "f"(a));
    return r;
}
__device__ __forceinline__ float bflo(uint32_t h) { return __uint_as_float(h << 16); }
__device__ __forceinline__ float bfhi(uint32_t h) { return __uint_as_float(h & 0xFFFF0000u); }

__device__ __forceinline__ void cp16(uint32_t dst, const void* src) {
    asm volatile("cp.async.cg.shared.global [%0], [%1], 16;" :: "r"(dst), "l"(src) : "memory");
}
#define CP_COMMIT() asm volatile("cp.async.commit_group;" ::: "memory")
#define CP_WAIT0()  asm volatile("cp.async.wait_group 0;" ::: "memory")

__device__ __forceinline__ void ldsm4(uint32_t* r, uint32_t addr) {
    asm volatile("ldmatrix.sync.aligned.m8n8.x4.shared.b16 {%0,%1,%2,%3}, [%4];"
                 : "=r"(r[0]), "=r"(r[1]), "=r"(r[2]), "=r"(r[3]) : "r"(addr));
}
__device__ __forceinline__ void mma_bf16(float* c, const uint32_t* a, const uint32_t* b) {
    asm volatile(
        "mma.sync.aligned.m16n8k16.row.col.f32.bf16.bf16.f32 "
        "{%0,%1,%2,%3}, {%4,%5,%6,%7}, {%8,%9}, {%0,%1,%2,%3};"
        : "+f"(c[0]), "+f"(c[1]), "+f"(c[2]), "+f"(c[3])
        : "r"(a[0]), "r"(a[1]), "r"(a[2]), "r"(a[3]), "r"(b[0]), "r"(b[1]));
}

// ================= W split precompute =================
__global__ void wsplit_kernel(const float* __restrict__ W) {
    int i = (blockIdx.x * blockDim.x + threadIdx.x) * 4;
    float4 v = *(const float4*)(W + i);
    uint32_t h0 = bf2pack(v.x, v.y), h1 = bf2pack(v.z, v.w);
    uint32_t m0 = bf2pack(v.x - bflo(h0), v.y - bfhi(h0));
    uint32_t m1 = bf2pack(v.z - bflo(h1), v.w - bfhi(h1));
    *(uint2*)(Wh_g + i) = make_uint2(h0, h1);
    *(uint2*)(Wm_g + i) = make_uint2(m0, m1);
}

// one pipelined k-tile: MMA(KT, stage SB) + prefetch(KT+1 -> stage SB^1)
#define TILE_STEP(FC, FN, KT, SB)                                              \
{                                                                              \
    const bool more = (KT) + 1 < ktiles;                                       \
    if (more) {                                                                \
        issueB((KT) + 1, (SB) ^ 1);                                            \
        const int kb0 = ((KT) + 1) * 64 + klane;                               \
        _Pragma("unroll")                                                      \
        for (int ks = 0; ks < 4; ks++) {                                       \
            raw[ks][0] = *(const float2*)(xr0 + kb0 + ks * 16);                \
            raw[ks][1] = *(const float2*)(xr8 + kb0 + ks * 16);                \
            raw[ks][2] = *(const float2*)(xr0 + kb0 + ks * 16 + 8);            \
            raw[ks][3] = *(const float2*)(xr8 + kb0 + ks * 16 + 8);            \
        }                                                                      \
    }                                                                          \
    CP_COMMIT();                                                               \
    {                                                                          \
        const uint32_t Bh = sb + OFF_SPLIT + (SB) * STG;                       \
        const uint32_t Bm = Bh + B_SPL;                                        \
        _Pragma("unroll")                                                      \
        for (int ks = 0; ks < 4; ks++) {                                       \
            uint32_t bh[8][2], bm[8][2], t4[4];                                \
            const uint32_t kb = (uint32_t)(ks * 32) + bh16;                    \
            _Pragma("unroll")                                                  \
            for (int g = 0; g < 4; g++) {                                      \
                ldsm4(t4, Bh + boff[g] + (kb ^ bqx[g]));                       \
                bh[2*g][0] = t4[0]; bh[2*g][1] = t4[1];                        \
                bh[2*g+1][0] = t4[2]; bh[2*g+1][1] = t4[3];                    \
                ldsm4(t4, Bm + boff[g] + (kb ^ bqx[g]));                       \
                bm[2*g][0] = t4[0]; bm[2*g][1] = t4[1];                        \
                bm[2*g+1][0] = t4[2]; bm[2*g+1][1] = t4[3];                    \
            }                                                                  \
            _Pragma("unroll")                                                  \
            for (int ni = 0; ni < 8; ni++) {                                   \
                mma_bf16(acc[ni], FC[0][ks], bh[ni]);  /* h*h */               \
                mma_bf16(acc[ni], FC[0][ks], bm[ni]);  /* h*m */               \
                mma_bf16(acc[ni], FC[1][ks], bh[ni]);  /* m*h */               \
            }                                                                  \
        }                                                                      \
    }                                                                          \
    if (more) {                                                                \
        _Pragma("unroll")                                                      \
        for (int ks = 0; ks < 4; ks++) {                                       \
            _Pragma("unroll")                                                  \
            for (int q = 0; q < 4; q++) {                                      \
                float2 v = raw[ks][q];                                         \
                uint32_t h = bf2pack(v.x, v.y);                                \
                FN[0][ks][q] = h;                                              \
                FN[1][ks][q] = bf2pack(v.x - bflo(h), v.y - bfhi(h));          \
            }                                                                  \
        }                                                                      \
        CP_WAIT0();                                                            \
        __syncthreads();                                                       \
    }                                                                          \
}

// ================= main kernel =================
__global__ __launch_bounds__(TH, 3)
void topk_gate_hmma_kernel(const float* __restrict__ x,
                           const float* __restrict__ W,
                           const float* __restrict__ bias,
                           float* __restrict__ out,
                           int N, int D, int write_idx) {
    __shared__ __align__(16) char smem[SMEM_BYTES];
    const uint32_t sb = s2u(smem);
    const int tid = threadIdx.x;
    const int lane = tid & 31;
    const int wid = tid >> 5;
    const int row0 = blockIdx.x * BM;

    if (tid < BN) ((float*)smem)[tid] = bias[tid];

    // ---- A direct-load geometry (mma fragment native layout) ----
    const int warprow = wid * 16 + (lane >> 2);
    const int klane = (lane & 3) * 2;
    const float* xr0 = x + (size_t)(row0 + warprow) * D;
    const float* xr8 = xr0 + 8 * (size_t)D;

    // ---- B ldsm geometry ----
    uint32_t boff[4], bqx[4];
#pragma unroll
    for (int g = 0; g < 4; g++) {
        int br = ((lane >> 4) << 3) + (lane & 7) + g * 16;
        boff[g] = (uint32_t)br * 144;
        bqx[g]  = ((uint32_t)(br >> 3) & 3) << 4;
    }
    const uint32_t bh16 = ((uint32_t)(lane >> 3) & 1) << 4;

    // ---- B cp.async producer ----
    auto issueB = [&](int kt, int s) {
        const uint32_t bsm = sb + OFF_SPLIT + s * STG;
#pragma unroll
        for (int j = 0; j < 8; j++) {
            int cid = tid + TH * j;            // 0..1023
            int spl = cid >> 9;                // 0: Bh, 1: Bm
            int rem = cid & 511;
            int n = rem >> 3, c = rem & 7;
            uint32_t qx = ((uint32_t)(n >> 3) & 3) << 4;
            uint32_t dst = bsm + spl * B_SPL + n * 144 + (((uint32_t)c * 16) ^ qx);
            const unsigned short* src =
                (spl ? Wm_g : Wh_g) + (size_t)n * D + (size_t)kt * 64 + c * 8;
            cp16(dst, src);
        }
    };

    float acc[8][4];
#pragma unroll
    for (int ni = 0; ni < 8; ni++)
#pragma unroll
        for (int q = 0; q < 4; q++) acc[ni][q] = 0.0f;

    uint32_t fA[2][4][4], fB[2][4][4];
    float2 raw[4][4];
    const int ktiles = D / 64;

    // ---- prolog: A tile 0 -> fA (regs), B tile 0 -> stage 0 ----
    issueB(0, 0);
    CP_COMMIT();
#pragma unroll
    for (int ks = 0; ks < 4; ks++) {
        raw[ks][0] = *(const float2*)(xr0 + klane + ks * 16);
        raw[ks][1] = *(const float2*)(xr8 + klane + ks * 16);
        raw[ks][2] = *(const float2*)(xr0 + klane + ks * 16 + 8);
        raw[ks][3] = *(const float2*)(xr8 + klane + ks * 16 + 8);
    }
#pragma unroll
    for (int ks = 0; ks < 4; ks++)
#pragma unroll
        for (int q = 0; q < 4; q++) {
            float2 v = raw[ks][q];
            uint32_t h = bf2pack(v.x, v.y);
            fA[0][ks][q] = h;
            fA[1][ks][q] = bf2pack(v.x - bflo(h), v.y - bfhi(h));
        }
    CP_WAIT0();
    __syncthreads();

    // ---- main loop (2 tiles per trip; compile-time stage index) ----
    for (int kt = 0; kt < ktiles; kt += 2) {
        TILE_STEP(fA, fB, kt, 0);
        TILE_STEP(fB, fA, kt + 1, 1);
    }

    // ---- epilogue: logits (+bias) -> Ls (reuses B area) ----
    float* Ls = (float*)(smem + OFF_SPLIT);
    const float* bias_sm = (const float*)smem;
    {
        const int r0 = wid * 16 + (lane >> 2);
        const int cbase = (lane & 3) * 2;
#pragma unroll
        for (int ni = 0; ni < 8; ni++) {
            int c = ni * 8 + cbase;
            float b0 = bias_sm[c], b1 = bias_sm[c + 1];
            *(float2*)(Ls + r0 * LS_LD + c) =
                make_float2(acc[ni][0] + b0, acc[ni][1] + b1);
            *(float2*)(Ls + (r0 + 8) * LS_LD + c) =
                make_float2(acc[ni][2] + b0, acc[ni][3] + b1);
        }
    }
    __syncthreads();

    // ---- per-row top-3 scan, exact fp32 rescue for narrow gaps, softmax ----
    if (tid < BM) {
        const float* lr = Ls + tid * LS_LD;
        float v1 = -INFINITY, v2 = -INFINITY, v3 = -INFINITY;
        int i1 = 0, i2 = 0;
#pragma unroll
        for (int j = 0; j < BN; j++) {
            float v = lr[j];
            if (v > v1)      { v3 = v2; v2 = v1; i2 = i1; v1 = v; i1 = j; }
            else if (v > v2) { v3 = v2; v2 = v; i2 = j; }
            else if (v > v3) { v3 = v; }
        }
        bool flag = (v1 - v2 < THRESH) || (v2 - v3 < THRESH);

        unsigned m = __ballot_sync(0xFFFFFFFFu, flag);
        while (m) {
            int rr = __ffs(m) - 1;
            m &= m - 1;
            int row = (wid << 5) + rr;
            const float4* xr = (const float4*)(x + (size_t)(row0 + row) * D);
            const float4* w0 = (const float4*)(W + (size_t)lane * D);
            const float4* w1 = (const float4*)(W + (size_t)(lane + 32) * D);
            float a0 = 0.f, a1 = 0.f;
            const int KQ = D / 4;
#pragma unroll 4
            for (int kq = 0; kq < KQ; kq++) {
                float4 xv = xr[kq], u = w0[kq], v = w1[kq];
                a0 = fmaf(xv.x, u.x, a0); a0 = fmaf(xv.y, u.y, a0);
                a0 = fmaf(xv.z, u.z, a0); a0 = fmaf(xv.w, u.w, a0);
                a1 = fmaf(xv.x, v.x, a1); a1 = fmaf(xv.y, v.y, a1);
                a1 = fmaf(xv.z, v.z, a1); a1 = fmaf(xv.w, v.w, a1);
            }
            float* wr = Ls + row * LS_LD;
            wr[lane]      = a0 + bias_sm[lane];
            wr[lane + 32] = a1 + bias_sm[lane + 32];
            __syncwarp();
        }
        if (flag) {
            v1 = -INFINITY; v2 = -INFINITY; i1 = 0; i2 = 0;
#pragma unroll
            for (int j = 0; j < BN; j++) {
                float v = lr[j];
                if (v > v1)      { v2 = v1; i2 = i1; v1 = v; i1 = j; }
                else if (v > v2) { v2 = v; i2 = j; }
            }
        }

        float e  = expf(v2 - v1);
        float p1 = 1.0f / (1.0f + e);
        float p2 = e * p1;

        float* orow = out + (size_t)(row0 + tid) * BN;
        float4 z = make_float4(0.f, 0.f, 0.f, 0.f);
#pragma unroll
        for (int q = 0; q < 16; q++) ((float4*)orow)[q] = z;
        orow[i1] = p1;
        orow[i2] = p2;

        if (write_idx) {
            float* oi = out + (size_t)N * BN + (size_t)(row0 + tid) * 2;
            oi[0] = (float)i1;
            oi[1] = (float)i2;
        }
    }
}

// ================= launch =================
extern "C" void kernel_launch(void* const* d_in, const int* in_sizes, int n_in,
                              void* d_out, int out_size) {
    const float* x    = (const float*)d_in[0];
    const float* W    = (const float*)d_in[1];
    const float* bias = (const float*)d_in[2];
    float* out = (float*)d_out;

    const int E = in_sizes[2];          // 64
    const int D = in_sizes[1] / E;      // 4096
    const int N = in_sizes[0] / D;      // 16384
    const int write_idx = (out_size >= N * E + 2 * N) ? 1 : 0;

    wsplit_kernel<<<(E * D) / (256 * 4), 256>>>(W);
    topk_gate_hmma_kernel<<<N / BM, TH>>>(x, W, bias, out, N, D, write_idx);
}

// round 15
// speedup vs baseline: 1.8745x; 1.0164x over previous
#include <cuda_runtime.h>
#include <math.h>
#include <stdint.h>

// ================= config =================
static constexpr int BM = 32;
static constexpr int BN = 64;
static constexpr int TH = 128;

static constexpr int B_SPL = 64 * 144;      // one bf16 split tile of B: 9216
static constexpr int STG   = 2 * B_SPL;     // Bh + Bm = 18432
static constexpr int OFF_SPLIT = 1024;      // header: bias
static constexpr int SMEM_BYTES = OFF_SPLIT + 2 * STG;   // 37888 (static)
static constexpr int LS_LD = 66;
#define THRESH 2e-4f

// precomputed bf16 splits of W (written by wsplit_kernel, read via cp.async)
__device__ unsigned short Wh_g[64 * 4096];
__device__ unsigned short Wm_g[64 * 4096];

// ================= ptx helpers (sm_80-level only) =================
__device__ __forceinline__ uint32_t s2u(const void* p) {
    uint32_t a;
    asm("{ .reg .u64 t; cvta.to.shared.u64 t, %1; cvt.u32.u64 %0, t; }"
        : "=r"(a) : "l"(p));
    return a;
}
__device__ __forceinline__ uint32_t bf2pack(float a, float b) {
    uint32_t r;
    asm("cvt.rn.bf16x2.f32 %0, %1, %2;" : "=r"(r) : "f"(b), "f"(a));
    return r;
}
__device__ __forceinline__ float bflo(uint32_t h) { return __uint_as_float(h << 16); }
__device__ __forceinline__ float bfhi(uint32_t h) { return __uint_as_float(h & 0xFFFF0000u); }

__device__ __forceinline__ void cp16(uint32_t dst, const void* src) {
    asm volatile("cp.async.cg.shared.global [%0], [%1], 16;" :: "r"(dst), "l"(src) : "memory");
}
#define CP_COMMIT() asm volatile("cp.async.commit_group;" ::: "memory")
#define CP_WAIT0()  asm volatile("cp.async.wait_group 0;" ::: "memory")

__device__ __forceinline__ void ldsm4(uint32_t* r, uint32_t addr) {
    asm volatile("ldmatrix.sync.aligned.m8n8.x4.shared.b16 {%0,%1,%2,%3}, [%4];"
                 : "=r"(r[0]), "=r"(r[1]), "=r"(r[2]), "=r"(r[3]) : "r"(addr));
}
__device__ __forceinline__ void mma_bf16(float* c, const uint32_t* a, const uint32_t* b) {
    asm volatile(
        "mma.sync.aligned.m16n8k16.row.col.f32.bf16.bf16.f32 "
        "{%0,%1,%2,%3}, {%4,%5,%6,%7}, {%8,%9}, {%0,%1,%2,%3};"
        : "+f"(c[0]), "+f"(c[1]), "+f"(c[2]), "+f"(c[3])
        : "r"(a[0]), "r"(a[1]), "r"(a[2]), "r"(a[3]), "r"(b[0]), "r"(b[1]));
}

// ================= W split precompute =================
__global__ void wsplit_kernel(const float* __restrict__ W) {
    int i = (blockIdx.x * blockDim.x + threadIdx.x) * 4;
    float4 v = *(const float4*)(W + i);
    uint32_t h0 = bf2pack(v.x, v.y), h1 = bf2pack(v.z, v.w);
    uint32_t m0 = bf2pack(v.x - bflo(h0), v.y - bfhi(h0));
    uint32_t m1 = bf2pack(v.z - bflo(h1), v.w - bfhi(h1));
    *(uint2*)(Wh_g + i) = make_uint2(h0, h1);
    *(uint2*)(Wm_g + i) = make_uint2(m0, m1);
}

// ================= main kernel =================
__global__ __launch_bounds__(TH, 4)
void topk_gate_hmma_kernel(const float* __restrict__ x,
                           const float* __restrict__ W,
                           const float* __restrict__ bias,
                           float* __restrict__ out,
                           int N, int D, int write_idx) {
    __shared__ __align__(16) char smem[SMEM_BYTES];
    const uint32_t sb = s2u(smem);
    const int tid = threadIdx.x;
    const int lane = tid & 31;
    const int wid = tid >> 5;
    const int row0 = blockIdx.x * BM;

    if (tid < BN) ((float*)smem)[tid] = bias[tid];

    // ---- warp layout: 2x2 (wm = M half, wn = N half) ----
    const int wm = wid >> 1, wn = wid & 1;

    // ---- A direct-load geometry (mma fragment native layout) ----
    const int warprow = wm * 16 + (lane >> 2);
    const int klane = (lane & 3) * 2;
    const float* xr0 = x + (size_t)(row0 + warprow) * D;
    const float* xr8 = xr0 + 8 * (size_t)D;

    // ---- B ldsm geometry (this warp's 32-col half) ----
    uint32_t boff[2], bqx[2];
#pragma unroll
    for (int g = 0; g < 2; g++) {
        int br = wn * 32 + ((lane >> 4) << 3) + (lane & 7) + g * 16;
        boff[g] = (uint32_t)br * 144;
        bqx[g]  = ((uint32_t)(br >> 3) & 3) << 4;
    }
    const uint32_t bh16 = ((uint32_t)(lane >> 3) & 1) << 4;

    // ---- B cp.async producer (full 64-expert tile, both splits) ----
    auto issueB = [&](int kt, int s) {
        const uint32_t bsm = sb + OFF_SPLIT + s * STG;
#pragma unroll
        for (int j = 0; j < 8; j++) {
            int cid = tid + TH * j;            // 0..1023
            int spl = cid >> 9;                // 0: Bh, 1: Bm
            int rem = cid & 511;
            int n = rem >> 3, c = rem & 7;
            uint32_t qx = ((uint32_t)(n >> 3) & 3) << 4;
            uint32_t dst = bsm + spl * B_SPL + n * 144 + (((uint32_t)c * 16) ^ qx);
            const unsigned short* src =
                (spl ? Wm_g : Wh_g) + (size_t)n * D + (size_t)kt * 64 + c * 8;
            cp16(dst, src);
        }
    };

    float acc[4][4];
#pragma unroll
    for (int ni = 0; ni < 4; ni++)
#pragma unroll
        for (int q = 0; q < 4; q++) acc[ni][q] = 0.0f;

    uint32_t fA[2][4][4];      // [split][ks][reg] for current tile
    float2 raw[4][2];          // staged fp32 A for next tile
    const int ktiles = D / 64;

    auto loadRaw = [&](int kt) {
        const int kb0 = kt * 64 + klane;
#pragma unroll
        for (int ks = 0; ks < 4; ks++) {
            raw[ks][0] = *(const float2*)(xr0 + kb0 + ks * 16);
            raw[ks][1] = *(const float2*)(xr0 + kb0 + ks * 16 + 8);
        }
        // rows +8 interleaved below to keep raw small: use xr8 into same regs later
    };
    (void)loadRaw;

    // full fragment needs rows r and r+8: stage them as two raw quads
    float2 raw8[4][2];

    auto loadRawFull = [&](int kt) {
        const int kb0 = kt * 64 + klane;
#pragma unroll
        for (int ks = 0; ks < 4; ks++) {
            raw[ks][0]  = *(const float2*)(xr0 + kb0 + ks * 16);
            raw[ks][1]  = *(const float2*)(xr0 + kb0 + ks * 16 + 8);
            raw8[ks][0] = *(const float2*)(xr8 + kb0 + ks * 16);
            raw8[ks][1] = *(const float2*)(xr8 + kb0 + ks * 16 + 8);
        }
    };
    auto convRaw = [&]() {
        // fragment reg order: {r, r+8, r(+k8), r+8(+k8)} -> regs 0..3
#pragma unroll
        for (int ks = 0; ks < 4; ks++) {
            float2 v0 = raw[ks][0], v1 = raw8[ks][0];
            float2 v2 = raw[ks][1], v3 = raw8[ks][1];
            uint32_t h0 = bf2pack(v0.x, v0.y), h1 = bf2pack(v1.x, v1.y);
            uint32_t h2 = bf2pack(v2.x, v2.y), h3 = bf2pack(v3.x, v3.y);
            fA[0][ks][0] = h0; fA[0][ks][1] = h1; fA[0][ks][2] = h2; fA[0][ks][3] = h3;
            fA[1][ks][0] = bf2pack(v0.x - bflo(h0), v0.y - bfhi(h0));
            fA[1][ks][1] = bf2pack(v1.x - bflo(h1), v1.y - bfhi(h1));
            fA[1][ks][2] = bf2pack(v2.x - bflo(h2), v2.y - bfhi(h2));
            fA[1][ks][3] = bf2pack(v3.x - bflo(h3), v3.y - bfhi(h3));
        }
    };

    // ---- prolog: A tile 0 -> fA, B tile 0 -> stage 0 ----
    issueB(0, 0);
    CP_COMMIT();
    loadRawFull(0);
    convRaw();
    CP_WAIT0();
    __syncthreads();

    // ---- main loop: 1 sync/tile ----
    for (int kt = 0; kt < ktiles; kt++) {
        const int s = kt & 1;
        const bool more = (kt + 1 < ktiles);
        if (more) {
            issueB(kt + 1, s ^ 1);
            loadRawFull(kt + 1);   // LDG latency hidden under the MMA block
        }
        CP_COMMIT();

        const uint32_t Bh = sb + OFF_SPLIT + s * STG;
        const uint32_t Bm = Bh + B_SPL;
#pragma unroll
        for (int ks = 0; ks < 4; ks++) {
            uint32_t bh[4][2], bm[4][2], t4[4];
            const uint32_t kb = (uint32_t)(ks * 32) + bh16;
#pragma unroll
            for (int g = 0; g < 2; g++) {
                ldsm4(t4, Bh + boff[g] + (kb ^ bqx[g]));
                bh[2 * g][0] = t4[0]; bh[2 * g][1] = t4[1];
                bh[2 * g + 1][0] = t4[2]; bh[2 * g + 1][1] = t4[3];
                ldsm4(t4, Bm + boff[g] + (kb ^ bqx[g]));
                bm[2 * g][0] = t4[0]; bm[2 * g][1] = t4[1];
                bm[2 * g + 1][0] = t4[2]; bm[2 * g + 1][1] = t4[3];
            }
#pragma unroll
            for (int ni = 0; ni < 4; ni++) {
                mma_bf16(acc[ni], fA[0][ks], bh[ni]);   // h*h
                mma_bf16(acc[ni], fA[0][ks], bm[ni]);   // h*m
                mma_bf16(acc[ni], fA[1][ks], bh[ni]);   // m*h
            }
        }
        if (more) {
            convRaw();             // overwrite fA with next tile's fragments
            CP_WAIT0();
            __syncthreads();
        }
    }

    // ---- epilogue: logits (+bias) -> Ls (stage-0 area; last tile used stage 1) ----
    float* Ls = (float*)(smem + OFF_SPLIT);
    const float* bias_sm = (const float*)smem;
    {
        const int r0 = wm * 16 + (lane >> 2);
        const int cbase = wn * 32 + (lane & 3) * 2;
#pragma unroll
        for (int ni = 0; ni < 4; ni++) {
            int c = cbase + ni * 8;
            float b0 = bias_sm[c], b1 = bias_sm[c + 1];
            *(float2*)(Ls + r0 * LS_LD + c) =
                make_float2(acc[ni][0] + b0, acc[ni][1] + b1);
            *(float2*)(Ls + (r0 + 8) * LS_LD + c) =
                make_float2(acc[ni][2] + b0, acc[ni][3] + b1);
        }
    }
    __syncthreads();

    // ---- per-row top-3 scan, exact fp32 rescue for narrow gaps, softmax ----
    if (tid < BM) {
        const float* lr = Ls + tid * LS_LD;
        float v1 = -INFINITY, v2 = -INFINITY, v3 = -INFINITY;
        int i1 = 0, i2 = 0;
#pragma unroll
        for (int j = 0; j < BN; j++) {
            float v = lr[j];
            if (v > v1)      { v3 = v2; v2 = v1; i2 = i1; v1 = v; i1 = j; }
            else if (v > v2) { v3 = v2; v2 = v; i2 = j; }
            else if (v > v3) { v3 = v; }
        }
        bool flag = (v1 - v2 < THRESH) || (v2 - v3 < THRESH);

        unsigned m = __ballot_sync(0xFFFFFFFFu, flag);
        while (m) {
            int rr = __ffs(m) - 1;
            m &= m - 1;
            const float4* xr = (const float4*)(x + (size_t)(row0 + rr) * D);
            const float4* w0 = (const float4*)(W + (size_t)lane * D);
            const float4* w1 = (const float4*)(W + (size_t)(lane + 32) * D);
            float a0 = 0.f, a1 = 0.f;
            const int KQ = D / 4;
#pragma unroll 4
            for (int kq = 0; kq < KQ; kq++) {
                float4 xv = xr[kq], u = w0[kq], v = w1[kq];
                a0 = fmaf(xv.x, u.x, a0); a0 = fmaf(xv.y, u.y, a0);
                a0 = fmaf(xv.z, u.z, a0); a0 = fmaf(xv.w, u.w, a0);
                a1 = fmaf(xv.x, v.x, a1); a1 = fmaf(xv.y, v.y, a1);
                a1 = fmaf(xv.z, v.z, a1); a1 = fmaf(xv.w, v.w, a1);
            }
            float* wr = Ls + rr * LS_LD;
            wr[lane]      = a0 + bias_sm[lane];
            wr[lane + 32] = a1 + bias_sm[lane + 32];
            __syncwarp();
        }
        if (flag) {
            v1 = -INFINITY; v2 = -INFINITY; i1 = 0; i2 = 0;
#pragma unroll
            for (int j = 0; j < BN; j++) {
                float v = lr[j];
                if (v > v1)      { v2 = v1; i2 = i1; v1 = v; i1 = j; }
                else if (v > v2) { v2 = v; i2 = j; }
            }
        }

        float e  = expf(v2 - v1);
        float p1 = 1.0f / (1.0f + e);
        float p2 = e * p1;

        float* orow = out + (size_t)(row0 + tid) * BN;
        float4 z = make_float4(0.f, 0.f, 0.f, 0.f);
#pragma unroll
        for (int q = 0; q < 16; q++) ((float4*)orow)[q] = z;
        orow[i1] = p1;
        orow[i2] = p2;

        if (write_idx) {
            float* oi = out + (size_t)N * BN + (size_t)(row0 + tid) * 2;
            oi[0] = (float)i1;
            oi[1] = (float)i2;
        }
    }
}

// ================= launch =================
extern "C" void kernel_launch(void* const* d_in, const int* in_sizes, int n_in,
                              void* d_out, int out_size) {
    const float* x    = (const float*)d_in[0];
    const float* W    = (const float*)d_in[1];
    const float* bias = (const float*)d_in[2];
    float* out = (float*)d_out;

    const int E = in_sizes[2];          // 64
    const int D = in_sizes[1] / E;      // 4096
    const int N = in_sizes[0] / D;      // 16384
    const int write_idx = (out_size >= N * E + 2 * N) ? 1 : 0;

    wsplit_kernel<<<(E * D) / (256 * 4), 256>>>(W);
    topk_gate_hmma_kernel<<<N / BM, TH>>>(x, W, bias, out, N, D, write_idx);
}

// round 16
// speedup vs baseline: 1.9502x; 1.0404x over previous
#include <cuda_runtime.h>
#include <math.h>
#include <stdint.h>

// ================= config =================
static constexpr int BM = 32;
static constexpr int BN = 64;
static constexpr int TH = 128;

static constexpr int B_SPL = 64 * 144;      // one bf16 split tile of B: 9216
static constexpr int STG   = 2 * B_SPL;     // Bh + Bm = 18432
static constexpr int OFF_SPLIT = 1024;      // header: bias
static constexpr int NSTAGE = 3;
static constexpr int SMEM_BYTES = OFF_SPLIT + NSTAGE * STG;   // 56320 (dynamic)
static constexpr int LS_LD = 66;
#define THRESH 2e-4f

// precomputed bf16 splits of W (written by wsplit_kernel, read via cp.async)
__device__ unsigned short Wh_g[64 * 4096];
__device__ unsigned short Wm_g[64 * 4096];

// ================= ptx helpers (sm_80-level only) =================
__device__ __forceinline__ uint32_t s2u(const void* p) {
    uint32_t a;
    asm("{ .reg .u64 t; cvta.to.shared.u64 t, %1; cvt.u32.u64 %0, t; }"
        : "=r"(a) : "l"(p));
    return a;
}
__device__ __forceinline__ uint32_t bf2pack(float a, float b) {
    uint32_t r;
    asm("cvt.rn.bf16x2.f32 %0, %1, %2;" : "=r"(r) : "f"(b), "f"(a));
    return r;
}
__device__ __forceinline__ float bflo(uint32_t h) { return __uint_as_float(h << 16); }
__device__ __forceinline__ float bfhi(uint32_t h) { return __uint_as_float(h & 0xFFFF0000u); }

__device__ __forceinline__ void cp16(uint32_t dst, const void* src) {
    asm volatile("cp.async.cg.shared.global [%0], [%1], 16;" :: "r"(dst), "l"(src) : "memory");
}
#define CP_COMMIT() asm volatile("cp.async.commit_group;" ::: "memory")
#define CP_WAIT1()  asm volatile("cp.async.wait_group 1;" ::: "memory")

__device__ __forceinline__ void ldsm4(uint32_t* r, uint32_t addr) {
    asm volatile("ldmatrix.sync.aligned.m8n8.x4.shared.b16 {%0,%1,%2,%3}, [%4];"
                 : "=r"(r[0]), "=r"(r[1]), "=r"(r[2]), "=r"(r[3]) : "r"(addr));
}
__device__ __forceinline__ void mma_bf16(float* c, const uint32_t* a, const uint32_t* b) {
    asm volatile(
        "mma.sync.aligned.m16n8k16.row.col.f32.bf16.bf16.f32 "
        "{%0,%1,%2,%3}, {%4,%5,%6,%7}, {%8,%9}, {%0,%1,%2,%3};"
        : "+f"(c[0]), "+f"(c[1]), "+f"(c[2]), "+f"(c[3])
        : "r"(a[0]), "r"(a[1]), "r"(a[2]), "r"(a[3]), "r"(b[0]), "r"(b[1]));
}

// ================= W split precompute =================
__global__ void wsplit_kernel(const float* __restrict__ W) {
    int i = (blockIdx.x * blockDim.x + threadIdx.x) * 4;
    float4 v = *(const float4*)(W + i);
    uint32_t h0 = bf2pack(v.x, v.y), h1 = bf2pack(v.z, v.w);
    uint32_t m0 = bf2pack(v.x - bflo(h0), v.y - bfhi(h0));
    uint32_t m1 = bf2pack(v.z - bflo(h1), v.w - bfhi(h1));
    *(uint2*)(Wh_g + i) = make_uint2(h0, h1);
    *(uint2*)(Wm_g + i) = make_uint2(m0, m1);
}

// ================= main kernel =================
__global__ __launch_bounds__(TH, 4)
void topk_gate_hmma_kernel(const float* __restrict__ x,
                           const float* __restrict__ W,
                           const float* __restrict__ bias,
                           float* __restrict__ out,
                           int N, int D, int write_idx) {
    extern __shared__ __align__(16) char smem[];
    const uint32_t sb = s2u(smem);
    const int tid = threadIdx.x;
    const int lane = tid & 31;
    const int wid = tid >> 5;
    const int row0 = blockIdx.x * BM;

    if (tid < BN) ((float*)smem)[tid] = bias[tid];

    // ---- warp layout: 2x2 (wm = M half, wn = N half) ----
    const int wm = wid >> 1, wn = wid & 1;

    // ---- A direct-load geometry (mma fragment native layout) ----
    const int warprow = wm * 16 + (lane >> 2);
    const int klane = (lane & 3) * 2;
    const float* xr0 = x + (size_t)(row0 + warprow) * D;
    const float* xr8 = xr0 + 8 * (size_t)D;

    // ---- B ldsm geometry (this warp's 32-col half) ----
    uint32_t boff[2], bqx[2];
#pragma unroll
    for (int g = 0; g < 2; g++) {
        int br = wn * 32 + ((lane >> 4) << 3) + (lane & 7) + g * 16;
        boff[g] = (uint32_t)br * 144;
        bqx[g]  = ((uint32_t)(br >> 3) & 3) << 4;
    }
    const uint32_t bh16 = ((uint32_t)(lane >> 3) & 1) << 4;

    // ---- B cp.async producer (full 64-expert tile, both splits) ----
    auto issueB = [&](int kt, int s) {
        const uint32_t bsm = sb + OFF_SPLIT + s * STG;
#pragma unroll
        for (int j = 0; j < 8; j++) {
            int cid = tid + TH * j;            // 0..1023
            int spl = cid >> 9;                // 0: Bh, 1: Bm
            int rem = cid & 511;
            int n = rem >> 3, c = rem & 7;
            uint32_t qx = ((uint32_t)(n >> 3) & 3) << 4;
            uint32_t dst = bsm + spl * B_SPL + n * 144 + (((uint32_t)c * 16) ^ qx);
            const unsigned short* src =
                (spl ? Wm_g : Wh_g) + (size_t)n * D + (size_t)kt * 64 + c * 8;
            cp16(dst, src);
        }
    };

    float acc[4][4];
#pragma unroll
    for (int ni = 0; ni < 4; ni++)
#pragma unroll
        for (int q = 0; q < 4; q++) acc[ni][q] = 0.0f;

    uint32_t fA[2][4][4];      // [split][ks][reg] for current tile
    float2 raw[4][2], raw8[4][2];
    const int ktiles = D / 64;

    auto loadRawFull = [&](int kt) {
        const int kb0 = kt * 64 + klane;
#pragma unroll
        for (int ks = 0; ks < 4; ks++) {
            raw[ks][0]  = *(const float2*)(xr0 + kb0 + ks * 16);
            raw[ks][1]  = *(const float2*)(xr0 + kb0 + ks * 16 + 8);
            raw8[ks][0] = *(const float2*)(xr8 + kb0 + ks * 16);
            raw8[ks][1] = *(const float2*)(xr8 + kb0 + ks * 16 + 8);
        }
    };
    auto convRaw = [&]() {
#pragma unroll
        for (int ks = 0; ks < 4; ks++) {
            float2 v0 = raw[ks][0], v1 = raw8[ks][0];
            float2 v2 = raw[ks][1], v3 = raw8[ks][1];
            uint32_t h0 = bf2pack(v0.x, v0.y), h1 = bf2pack(v1.x, v1.y);
            uint32_t h2 = bf2pack(v2.x, v2.y), h3 = bf2pack(v3.x, v3.y);
            fA[0][ks][0] = h0; fA[0][ks][1] = h1; fA[0][ks][2] = h2; fA[0][ks][3] = h3;
            fA[1][ks][0] = bf2pack(v0.x - bflo(h0), v0.y - bfhi(h0));
            fA[1][ks][1] = bf2pack(v1.x - bflo(h1), v1.y - bfhi(h1));
            fA[1][ks][2] = bf2pack(v2.x - bflo(h2), v2.y - bfhi(h2));
            fA[1][ks][3] = bf2pack(v3.x - bflo(h3), v3.y - bfhi(h3));
        }
    };

    // ---- prolog: B tiles 0,1 in flight; A tile 0 -> fA ----
    issueB(0, 0);
    CP_COMMIT();
    if (ktiles > 1) issueB(1, 1);
    CP_COMMIT();
    loadRawFull(0);
    convRaw();
    CP_WAIT1();              // B(0) landed; B(1) may still fly
    __syncthreads();

    // ---- main loop: stage rotates mod 3; wait is one tile behind ----
    int s = 0, si = 2;       // current stage, issue-target stage (kt+2)
    for (int kt = 0; kt < ktiles; kt++) {
        const bool moreA = (kt + 1 < ktiles);
        if (kt + 2 < ktiles) issueB(kt + 2, si);
        if (moreA) loadRawFull(kt + 1);    // LDG latency hidden under MMAs
        CP_COMMIT();

        const uint32_t Bh = sb + OFF_SPLIT + s * STG;
        const uint32_t Bm = Bh + B_SPL;
#pragma unroll
        for (int ks = 0; ks < 4; ks++) {
            uint32_t bh[4][2], bm[4][2], t4[4];
            const uint32_t kb = (uint32_t)(ks * 32) + bh16;
#pragma unroll
            for (int g = 0; g < 2; g++) {
                ldsm4(t4, Bh + boff[g] + (kb ^ bqx[g]));
                bh[2 * g][0] = t4[0]; bh[2 * g][1] = t4[1];
                bh[2 * g + 1][0] = t4[2]; bh[2 * g + 1][1] = t4[3];
                ldsm4(t4, Bm + boff[g] + (kb ^ bqx[g]));
                bm[2 * g][0] = t4[0]; bm[2 * g][1] = t4[1];
                bm[2 * g + 1][0] = t4[2]; bm[2 * g + 1][1] = t4[3];
            }
            // combo-outer / ni-inner: same-acc reuse distance = 4 (ILP)
#pragma unroll
            for (int ni = 0; ni < 4; ni++) mma_bf16(acc[ni], fA[0][ks], bh[ni]);
#pragma unroll
            for (int ni = 0; ni < 4; ni++) mma_bf16(acc[ni], fA[0][ks], bm[ni]);
#pragma unroll
            for (int ni = 0; ni < 4; ni++) mma_bf16(acc[ni], fA[1][ks], bh[ni]);
        }
        if (moreA) {
            convRaw();
            CP_WAIT1();      // only needs B(kt+1); B(kt+2) still in flight
            __syncthreads();
        }
        s  = (s  == NSTAGE - 1) ? 0 : s + 1;
        si = (si == NSTAGE - 1) ? 0 : si + 1;
    }
    __syncthreads();         // all MMAs done before Ls reuses stage area

    // ---- epilogue: logits (+bias) -> Ls ----
    float* Ls = (float*)(smem + OFF_SPLIT);
    const float* bias_sm = (const float*)smem;
    {
        const int r0 = wm * 16 + (lane >> 2);
        const int cbase = wn * 32 + (lane & 3) * 2;
#pragma unroll
        for (int ni = 0; ni < 4; ni++) {
            int c = cbase + ni * 8;
            float b0 = bias_sm[c], b1 = bias_sm[c + 1];
            *(float2*)(Ls + r0 * LS_LD + c) =
                make_float2(acc[ni][0] + b0, acc[ni][1] + b1);
            *(float2*)(Ls + (r0 + 8) * LS_LD + c) =
                make_float2(acc[ni][2] + b0, acc[ni][3] + b1);
        }
    }
    __syncthreads();

    // ---- per-row top-3 scan, exact fp32 rescue for narrow gaps, softmax ----
    if (tid < BM) {
        const float* lr = Ls + tid * LS_LD;
        float v1 = -INFINITY, v2 = -INFINITY, v3 = -INFINITY;
        int i1 = 0, i2 = 0;
#pragma unroll
        for (int j = 0; j < BN; j++) {
            float v = lr[j];
            if (v > v1)      { v3 = v2; v2 = v1; i2 = i1; v1 = v; i1 = j; }
            else if (v > v2) { v3 = v2; v2 = v; i2 = j; }
            else if (v > v3) { v3 = v; }
        }
        bool flag = (v1 - v2 < THRESH) || (v2 - v3 < THRESH);

        unsigned m = __ballot_sync(0xFFFFFFFFu, flag);
        while (m) {
            int rr = __ffs(m) - 1;
            m &= m - 1;
            const float4* xr = (const float4*)(x + (size_t)(row0 + rr) * D);
            const float4* w0 = (const float4*)(W + (size_t)lane * D);
            const float4* w1 = (const float4*)(W + (size_t)(lane + 32) * D);
            float a0 = 0.f, a1 = 0.f;
            const int KQ = D / 4;
#pragma unroll 4
            for (int kq = 0; kq < KQ; kq++) {
                float4 xv = xr[kq], u = w0[kq], v = w1[kq];
                a0 = fmaf(xv.x, u.x, a0); a0 = fmaf(xv.y, u.y, a0);
                a0 = fmaf(xv.z, u.z, a0); a0 = fmaf(xv.w, u.w, a0);
                a1 = fmaf(xv.x, v.x, a1); a1 = fmaf(xv.y, v.y, a1);
                a1 = fmaf(xv.z, v.z, a1); a1 = fmaf(xv.w, v.w, a1);
            }
            float* wr = Ls + rr * LS_LD;
            wr[lane]      = a0 + bias_sm[lane];
            wr[lane + 32] = a1 + bias_sm[lane + 32];
            __syncwarp();
        }
        if (flag) {
            v1 = -INFINITY; v2 = -INFINITY; i1 = 0; i2 = 0;
#pragma unroll
            for (int j = 0; j < BN; j++) {
                float v = lr[j];
                if (v > v1)      { v2 = v1; i2 = i1; v1 = v; i1 = j; }
                else if (v > v2) { v2 = v; i2 = j; }
            }
        }

        float e  = expf(v2 - v1);
        float p1 = 1.0f / (1.0f + e);
        float p2 = e * p1;

        float* orow = out + (size_t)(row0 + tid) * BN;
        float4 z = make_float4(0.f, 0.f, 0.f, 0.f);
#pragma unroll
        for (int q = 0; q < 16; q++) ((float4*)orow)[q] = z;
        orow[i1] = p1;
        orow[i2] = p2;

        if (write_idx) {
            float* oi = out + (size_t)N * BN + (size_t)(row0 + tid) * 2;
            oi[0] = (float)i1;
            oi[1] = (float)i2;
        }
    }
}

// ================= launch =================
extern "C" void kernel_launch(void* const* d_in, const int* in_sizes, int n_in,
                              void* d_out, int out_size) {
    const float* x    = (const float*)d_in[0];
    const float* W    = (const float*)d_in[1];
    const float* bias = (const float*)d_in[2];
    float* out = (float*)d_out;

    const int E = in_sizes[2];          // 64
    const int D = in_sizes[1] / E;      // 4096
    const int N = in_sizes[0] / D;      // 16384
    const int write_idx = (out_size >= N * E + 2 * N) ? 1 : 0;

    wsplit_kernel<<<(E * D) / (256 * 4), 256>>>(W);
    cudaFuncSetAttribute(topk_gate_hmma_kernel,
                         cudaFuncAttributeMaxDynamicSharedMemorySize, SMEM_BYTES);
    topk_gate_hmma_kernel<<<N / BM, TH, SMEM_BYTES>>>(x, W, bias, out, N, D, write_idx);
}

// round 17
// speedup vs baseline: 2.0779x; 1.0655x over previous
#include <cuda_runtime.h>
#include <math.h>
#include <stdint.h>

// ================= config =================
static constexpr int BM = 64;
static constexpr int BN = 64;
static constexpr int TH = 128;

static constexpr int B_SPL = 64 * 144;      // one bf16 split tile of B: 9216
static constexpr int STG   = 2 * B_SPL;     // Bh + Bm = 18432
static constexpr int OFF_SPLIT = 1024;      // header: bias
static constexpr int NSTAGE = 3;
static constexpr int SMEM_BYTES = OFF_SPLIT + NSTAGE * STG;   // 56320 (dynamic)
static constexpr int LS_LD = 66;
#define THRESH 2e-4f

// precomputed bf16 splits of W (written by wsplit_kernel, read via cp.async)
__device__ unsigned short Wh_g[64 * 4096];
__device__ unsigned short Wm_g[64 * 4096];

// ================= ptx helpers (sm_80-level only) =================
__device__ __forceinline__ uint32_t s2u(const void* p) {
    uint32_t a;
    asm("{ .reg .u64 t; cvta.to.shared.u64 t, %1; cvt.u32.u64 %0, t; }"
        : "=r"(a) : "l"(p));
    return a;
}
__device__ __forceinline__ uint32_t bf2pack(float a, float b) {
    uint32_t r;
    asm("cvt.rn.bf16x2.f32 %0, %1, %2;" : "=r"(r) : "f"(b), "f"(a));
    return r;
}
__device__ __forceinline__ float bflo(uint32_t h) { return __uint_as_float(h << 16); }
__device__ __forceinline__ float bfhi(uint32_t h) { return __uint_as_float(h & 0xFFFF0000u); }

__device__ __forceinline__ void cp16(uint32_t dst, const void* src) {
    asm volatile("cp.async.cg.shared.global [%0], [%1], 16;" :: "r"(dst), "l"(src) : "memory");
}
#define CP_COMMIT() asm volatile("cp.async.commit_group;" ::: "memory")
#define CP_WAIT1()  asm volatile("cp.async.wait_group 1;" ::: "memory")

__device__ __forceinline__ void ldsm4(uint32_t* r, uint32_t addr) {
    asm volatile("ldmatrix.sync.aligned.m8n8.x4.shared.b16 {%0,%1,%2,%3}, [%4];"
                 : "=r"(r[0]), "=r"(r[1]), "=r"(r[2]), "=r"(r[3]) : "r"(addr));
}
__device__ __forceinline__ void mma_bf16(float* c, const uint32_t* a, const uint32_t* b) {
    asm volatile(
        "mma.sync.aligned.m16n8k16.row.col.f32.bf16.bf16.f32 "
        "{%0,%1,%2,%3}, {%4,%5,%6,%7}, {%8,%9}, {%0,%1,%2,%3};"
        : "+f"(c[0]), "+f"(c[1]), "+f"(c[2]), "+f"(c[3])
        : "r"(a[0]), "r"(a[1]), "r"(a[2]), "r"(a[3]), "r"(b[0]), "r"(b[1]));
}

// ================= W split precompute =================
__global__ void wsplit_kernel(const float* __restrict__ W) {
    int i = (blockIdx.x * blockDim.x + threadIdx.x) * 4;
    float4 v = *(const float4*)(W + i);
    uint32_t h0 = bf2pack(v.x, v.y), h1 = bf2pack(v.z, v.w);
    uint32_t m0 = bf2pack(v.x - bflo(h0), v.y - bfhi(h0));
    uint32_t m1 = bf2pack(v.z - bflo(h1), v.w - bfhi(h1));
    *(uint2*)(Wh_g + i) = make_uint2(h0, h1);
    *(uint2*)(Wm_g + i) = make_uint2(m0, m1);
}

// ================= main kernel =================
__global__ __launch_bounds__(TH, 2)
void topk_gate_hmma_kernel(const float* __restrict__ x,
                           const float* __restrict__ W,
                           const float* __restrict__ bias,
                           float* __restrict__ out,
                           int N, int D, int write_idx) {
    extern __shared__ __align__(16) char smem[];
    const uint32_t sb = s2u(smem);
    const int tid = threadIdx.x;
    const int lane = tid & 31;
    const int wid = tid >> 5;
    const int row0 = blockIdx.x * BM;

    if (tid < BN) ((float*)smem)[tid] = bias[tid];

    // ---- warp layout: 4 warps along M; each warp = 16 rows x all 64 experts ----
    const int warprow = wid * 16 + (lane >> 2);
    const int klane = (lane & 3) * 2;
    const float* xr0 = x + (size_t)(row0 + warprow) * D;
    const float* xr8 = xr0 + 8 * (size_t)D;

    // ---- B ldsm geometry (full 64 cols: 4 groups of 16) ----
    uint32_t boff[4], bqx[4];
#pragma unroll
    for (int g = 0; g < 4; g++) {
        int br = ((lane >> 4) << 3) + (lane & 7) + g * 16;
        boff[g] = (uint32_t)br * 144;
        bqx[g]  = ((uint32_t)(br >> 3) & 3) << 4;
    }
    const uint32_t bh16 = ((uint32_t)(lane >> 3) & 1) << 4;

    // ---- B cp.async producer (full 64-expert tile, both splits) ----
    auto issueB = [&](int kt, int s) {
        const uint32_t bsm = sb + OFF_SPLIT + s * STG;
#pragma unroll
        for (int j = 0; j < 8; j++) {
            int cid = tid + TH * j;            // 0..1023
            int spl = cid >> 9;                // 0: Bh, 1: Bm
            int rem = cid & 511;
            int n = rem >> 3, c = rem & 7;
            uint32_t qx = ((uint32_t)(n >> 3) & 3) << 4;
            uint32_t dst = bsm + spl * B_SPL + n * 144 + (((uint32_t)c * 16) ^ qx);
            const unsigned short* src =
                (spl ? Wm_g : Wh_g) + (size_t)n * D + (size_t)kt * 64 + c * 8;
            cp16(dst, src);
        }
    };

    float acc[8][4];
#pragma unroll
    for (int ni = 0; ni < 8; ni++)
#pragma unroll
        for (int q = 0; q < 4; q++) acc[ni][q] = 0.0f;

    uint32_t fA[2][4][4];      // [split][ks][reg] for current tile
    float2 raw[4][2], raw8[4][2];
    const int ktiles = D / 64;

    auto loadRawFull = [&](int kt) {
        const int kb0 = kt * 64 + klane;
#pragma unroll
        for (int ks = 0; ks < 4; ks++) {
            raw[ks][0]  = *(const float2*)(xr0 + kb0 + ks * 16);
            raw[ks][1]  = *(const float2*)(xr0 + kb0 + ks * 16 + 8);
            raw8[ks][0] = *(const float2*)(xr8 + kb0 + ks * 16);
            raw8[ks][1] = *(const float2*)(xr8 + kb0 + ks * 16 + 8);
        }
    };
    auto convRaw = [&]() {
#pragma unroll
        for (int ks = 0; ks < 4; ks++) {
            float2 v0 = raw[ks][0], v1 = raw8[ks][0];
            float2 v2 = raw[ks][1], v3 = raw8[ks][1];
            uint32_t h0 = bf2pack(v0.x, v0.y), h1 = bf2pack(v1.x, v1.y);
            uint32_t h2 = bf2pack(v2.x, v2.y), h3 = bf2pack(v3.x, v3.y);
            fA[0][ks][0] = h0; fA[0][ks][1] = h1; fA[0][ks][2] = h2; fA[0][ks][3] = h3;
            fA[1][ks][0] = bf2pack(v0.x - bflo(h0), v0.y - bfhi(h0));
            fA[1][ks][1] = bf2pack(v1.x - bflo(h1), v1.y - bfhi(h1));
            fA[1][ks][2] = bf2pack(v2.x - bflo(h2), v2.y - bfhi(h2));
            fA[1][ks][3] = bf2pack(v3.x - bflo(h3), v3.y - bfhi(h3));
        }
    };

    // ---- prolog: B tiles 0,1 in flight; A tile 0 -> fA ----
    issueB(0, 0);
    CP_COMMIT();
    if (ktiles > 1) issueB(1, 1);
    CP_COMMIT();
    loadRawFull(0);
    convRaw();
    CP_WAIT1();              // B(0) landed; B(1) may still fly
    __syncthreads();

    // ---- main loop: stage rotates mod 3; wait is one tile behind ----
    int s = 0, si = 2;       // current stage, issue-target stage (kt+2)
    for (int kt = 0; kt < ktiles; kt++) {
        const bool moreA = (kt + 1 < ktiles);
        if (kt + 2 < ktiles) issueB(kt + 2, si);
        if (moreA) loadRawFull(kt + 1);    // LDG latency hidden under MMAs
        CP_COMMIT();

        const uint32_t Bh = sb + OFF_SPLIT + s * STG;
        const uint32_t Bm = Bh + B_SPL;
#pragma unroll
        for (int ks = 0; ks < 4; ks++) {
            uint32_t bh[8][2], bm[8][2], t4[4];
            const uint32_t kb = (uint32_t)(ks * 32) + bh16;
#pragma unroll
            for (int g = 0; g < 4; g++) {
                ldsm4(t4, Bh + boff[g] + (kb ^ bqx[g]));
                bh[2 * g][0] = t4[0]; bh[2 * g][1] = t4[1];
                bh[2 * g + 1][0] = t4[2]; bh[2 * g + 1][1] = t4[3];
                ldsm4(t4, Bm + boff[g] + (kb ^ bqx[g]));
                bm[2 * g][0] = t4[0]; bm[2 * g][1] = t4[1];
                bm[2 * g + 1][0] = t4[2]; bm[2 * g + 1][1] = t4[3];
            }
            // combo-outer / ni-inner: same-acc reuse distance = 8 (deep ILP)
#pragma unroll
            for (int ni = 0; ni < 8; ni++) mma_bf16(acc[ni], fA[0][ks], bh[ni]);
#pragma unroll
            for (int ni = 0; ni < 8; ni++) mma_bf16(acc[ni], fA[0][ks], bm[ni]);
#pragma unroll
            for (int ni = 0; ni < 8; ni++) mma_bf16(acc[ni], fA[1][ks], bh[ni]);
        }
        if (moreA) {
            convRaw();
            CP_WAIT1();      // only needs B(kt+1); B(kt+2) still in flight
            __syncthreads();
        }
        s  = (s  == NSTAGE - 1) ? 0 : s + 1;
        si = (si == NSTAGE - 1) ? 0 : si + 1;
    }
    __syncthreads();         // all MMAs done before Ls reuses stage area

    // ---- epilogue: logits (+bias) -> Ls ----
    float* Ls = (float*)(smem + OFF_SPLIT);
    const float* bias_sm = (const float*)smem;
    {
        const int r0 = wid * 16 + (lane >> 2);
        const int cbase = (lane & 3) * 2;
#pragma unroll
        for (int ni = 0; ni < 8; ni++) {
            int c = cbase + ni * 8;
            float b0 = bias_sm[c], b1 = bias_sm[c + 1];
            *(float2*)(Ls + r0 * LS_LD + c) =
                make_float2(acc[ni][0] + b0, acc[ni][1] + b1);
            *(float2*)(Ls + (r0 + 8) * LS_LD + c) =
                make_float2(acc[ni][2] + b0, acc[ni][3] + b1);
        }
    }
    __syncthreads();

    // ---- per-row top-3 scan, exact fp32 rescue for narrow gaps, softmax ----
    if (tid < BM) {
        const float* lr = Ls + tid * LS_LD;
        float v1 = -INFINITY, v2 = -INFINITY, v3 = -INFINITY;
        int i1 = 0, i2 = 0;
#pragma unroll
        for (int j = 0; j < BN; j++) {
            float v = lr[j];
            if (v > v1)      { v3 = v2; v2 = v1; i2 = i1; v1 = v; i1 = j; }
            else if (v > v2) { v3 = v2; v2 = v; i2 = j; }
            else if (v > v3) { v3 = v; }
        }
        bool flag = (v1 - v2 < THRESH) || (v2 - v3 < THRESH);

        unsigned m = __ballot_sync(0xFFFFFFFFu, flag);
        while (m) {
            int rr = __ffs(m) - 1;
            m &= m - 1;
            int row = (wid << 5) + rr;
            const float4* xr = (const float4*)(x + (size_t)(row0 + row) * D);
            const float4* w0 = (const float4*)(W + (size_t)lane * D);
            const float4* w1 = (const float4*)(W + (size_t)(lane + 32) * D);
            float a0 = 0.f, a1 = 0.f;
            const int KQ = D / 4;
#pragma unroll 4
            for (int kq = 0; kq < KQ; kq++) {
                float4 xv = xr[kq], u = w0[kq], v = w1[kq];
                a0 = fmaf(xv.x, u.x, a0); a0 = fmaf(xv.y, u.y, a0);
                a0 = fmaf(xv.z, u.z, a0); a0 = fmaf(xv.w, u.w, a0);
                a1 = fmaf(xv.x, v.x, a1); a1 = fmaf(xv.y, v.y, a1);
                a1 = fmaf(xv.z, v.z, a1); a1 = fmaf(xv.w, v.w, a1);
            }
            float* wr = Ls + row * LS_LD;
            wr[lane]      = a0 + bias_sm[lane];
            wr[lane + 32] = a1 + bias_sm[lane + 32];
            __syncwarp();
        }
        if (flag) {
            v1 = -INFINITY; v2 = -INFINITY; i1 = 0; i2 = 0;
#pragma unroll
            for (int j = 0; j < BN; j++) {
                float v = lr[j];
                if (v > v1)      { v2 = v1; i2 = i1; v1 = v; i1 = j; }
                else if (v > v2) { v2 = v; i2 = j; }
            }
        }

        float e  = expf(v2 - v1);
        float p1 = 1.0f / (1.0f + e);
        float p2 = e * p1;

        float* orow = out + (size_t)(row0 + tid) * BN;
        float4 z = make_float4(0.f, 0.f, 0.f, 0.f);
#pragma unroll
        for (int q = 0; q < 16; q++) ((float4*)orow)[q] = z;
        orow[i1] = p1;
        orow[i2] = p2;

        if (write_idx) {
            float* oi = out + (size_t)N * BN + (size_t)(row0 + tid) * 2;
            oi[0] = (float)i1;
            oi[1] = (float)i2;
        }
    }
}

// ================= launch =================
extern "C" void kernel_launch(void* const* d_in, const int* in_sizes, int n_in,
                              void* d_out, int out_size) {
    const float* x    = (const float*)d_in[0];
    const float* W    = (const float*)d_in[1];
    const float* bias = (const float*)d_in[2];
    float* out = (float*)d_out;

    const int E = in_sizes[2];          // 64
    const int D = in_sizes[1] / E;      // 4096
    const int N = in_sizes[0] / D;      // 16384
    const int write_idx = (out_size >= N * E + 2 * N) ? 1 : 0;

    wsplit_kernel<<<(E * D) / (256 * 4), 256>>>(W);
    cudaFuncSetAttribute(topk_gate_hmma_kernel,
                         cudaFuncAttributeMaxDynamicSharedMemorySize, SMEM_BYTES);
    topk_gate_hmma_kernel<<<N / BM, TH, SMEM_BYTES>>>(x, W, bias, out, N, D, write_idx);
}